// round 1
// baseline (speedup 1.0000x reference)
#include <cuda_runtime.h>
#include <math.h>

#define HEADS 4
#define DOT   64
#define DIN   40
#define NMAX  501760   // N = 500000 with slack

// Folded projection: V[c][h] = sum_d W_k[c, h*64+d] * W_q[h,d] * (1/sqrt(64))
__device__ float g_V[DIN * HEADS];
// Scratch: z[n][h] pre-softmax logits
__device__ float g_z[(size_t)NMAX * HEADS];

// ---------------------------------------------------------------------------
// Kernel 1: fold W_k (rows 0..39, the "inputs" part of combined) with W_q.
// The agg part (rows 40..167) contributes a per-(segment,head) constant that
// cancels in the segment softmax, so it is never computed.
// ---------------------------------------------------------------------------
__global__ void k_fold(const float* __restrict__ Wk, const float* __restrict__ Wq) {
    int t = threadIdx.x;
    if (t < DIN * HEADS) {
        int c = t >> 2;      // 0..39
        int h = t & 3;       // 0..3
        float s = 0.f;
#pragma unroll
        for (int d = 0; d < DOT; d++)
            s += Wk[c * (HEADS * DOT) + h * DOT + d] * Wq[h * DOT + d];
        g_V[c * HEADS + h] = s * 0.125f;   // 1/sqrt(64)
    }
}

// ---------------------------------------------------------------------------
// Kernel 2: z[n,h] = x[n,:40] @ V[:,h].  One thread per row, float4 loads
// (row stride 160 B is 16B-aligned). HBM-bound: 80 MB in, 8 MB out.
// ---------------------------------------------------------------------------
__global__ void k_z(const float* __restrict__ x, float* __restrict__ z, int N) {
    __shared__ float Vs[DIN * HEADS];
    if (threadIdx.x < DIN * HEADS) Vs[threadIdx.x] = g_V[threadIdx.x];
    __syncthreads();

    int n = blockIdx.x * blockDim.x + threadIdx.x;
    if (n >= N) return;

    const float4* xr = reinterpret_cast<const float4*>(x) + (size_t)n * (DIN / 4);
    float a0 = 0.f, a1 = 0.f, a2 = 0.f, a3 = 0.f;
#pragma unroll
    for (int q = 0; q < DIN / 4; q++) {
        float4 v = xr[q];
        const float* Vp = &Vs[q * 16];
        a0 += v.x * Vp[0];  a1 += v.x * Vp[1];  a2 += v.x * Vp[2];  a3 += v.x * Vp[3];
        a0 += v.y * Vp[4];  a1 += v.y * Vp[5];  a2 += v.y * Vp[6];  a3 += v.y * Vp[7];
        a0 += v.z * Vp[8];  a1 += v.z * Vp[9];  a2 += v.z * Vp[10]; a3 += v.z * Vp[11];
        a0 += v.w * Vp[12]; a1 += v.w * Vp[13]; a2 += v.w * Vp[14]; a3 += v.w * Vp[15];
    }
    reinterpret_cast<float4*>(z)[n] = make_float4(a0, a1, a2, a3);
}

// ---------------------------------------------------------------------------
// Kernel 3: per-segment softmax (segments are contiguous since segment_ids
// is sorted). One block per segment; bounds via binary search; 3 streaming
// passes over ~244 rows (z slice stays L2/L1 hot). Writes out[h*N + n].
// ---------------------------------------------------------------------------
__inline__ __device__ float warpMax(float v) {
#pragma unroll
    for (int o = 16; o > 0; o >>= 1) v = fmaxf(v, __shfl_xor_sync(0xffffffffu, v, o));
    return v;
}
__inline__ __device__ float warpSum(float v) {
#pragma unroll
    for (int o = 16; o > 0; o >>= 1) v += __shfl_xor_sync(0xffffffffu, v, o);
    return v;
}

#define SOFT_THREADS 256
#define SOFT_WARPS   (SOFT_THREADS / 32)

__global__ void k_softmax(const float* __restrict__ z, const int* __restrict__ seg,
                          float* __restrict__ out, int N) {
    const int s = blockIdx.x;
    __shared__ int   sb[2];
    __shared__ float red[SOFT_WARPS][4];
    __shared__ float fin[8];   // [0..3]=max, [4..7]=1/sum

    if (threadIdx.x == 0) {
        int lo = 0, hi = N;
        while (lo < hi) { int md = (lo + hi) >> 1; if (seg[md] < s) lo = md + 1; else hi = md; }
        sb[0] = lo;
        hi = N;                           // lower_bound for s+1, start at sb[0]
        while (lo < hi) { int md = (lo + hi) >> 1; if (seg[md] <= s) lo = md + 1; else hi = md; }
        sb[1] = lo;
    }
    __syncthreads();
    const int st = sb[0], en = sb[1];
    if (en <= st) return;                 // uniform over block: safe

    const int wid = threadIdx.x >> 5, lane = threadIdx.x & 31;

    // ---- pass 1: per-head max ----
    float m[4] = {-1e30f, -1e30f, -1e30f, -1e30f};
    for (int i = st + threadIdx.x; i < en; i += SOFT_THREADS) {
        float4 v = reinterpret_cast<const float4*>(z)[i];
        m[0] = fmaxf(m[0], v.x); m[1] = fmaxf(m[1], v.y);
        m[2] = fmaxf(m[2], v.z); m[3] = fmaxf(m[3], v.w);
    }
#pragma unroll
    for (int k = 0; k < 4; k++) m[k] = warpMax(m[k]);
    if (lane == 0) { red[wid][0] = m[0]; red[wid][1] = m[1]; red[wid][2] = m[2]; red[wid][3] = m[3]; }
    __syncthreads();
    if (threadIdx.x == 0) {
        float r0 = red[0][0], r1 = red[0][1], r2 = red[0][2], r3 = red[0][3];
        for (int w = 1; w < SOFT_WARPS; w++) {
            r0 = fmaxf(r0, red[w][0]); r1 = fmaxf(r1, red[w][1]);
            r2 = fmaxf(r2, red[w][2]); r3 = fmaxf(r3, red[w][3]);
        }
        fin[0] = r0; fin[1] = r1; fin[2] = r2; fin[3] = r3;
    }
    __syncthreads();
    const float M0 = fin[0], M1 = fin[1], M2 = fin[2], M3 = fin[3];

    // ---- pass 2: per-head sum of exp ----
    float sm[4] = {0.f, 0.f, 0.f, 0.f};
    for (int i = st + threadIdx.x; i < en; i += SOFT_THREADS) {
        float4 v = reinterpret_cast<const float4*>(z)[i];
        sm[0] += expf(v.x - M0); sm[1] += expf(v.y - M1);
        sm[2] += expf(v.z - M2); sm[3] += expf(v.w - M3);
    }
#pragma unroll
    for (int k = 0; k < 4; k++) sm[k] = warpSum(sm[k]);
    __syncthreads();   // red reuse
    if (lane == 0) { red[wid][0] = sm[0]; red[wid][1] = sm[1]; red[wid][2] = sm[2]; red[wid][3] = sm[3]; }
    __syncthreads();
    if (threadIdx.x == 0) {
        float r0 = 0.f, r1 = 0.f, r2 = 0.f, r3 = 0.f;
        for (int w = 0; w < SOFT_WARPS; w++) {
            r0 += red[w][0]; r1 += red[w][1]; r2 += red[w][2]; r3 += red[w][3];
        }
        fin[4] = 1.f / r0; fin[5] = 1.f / r1; fin[6] = 1.f / r2; fin[7] = 1.f / r3;
    }
    __syncthreads();
    const float R0 = fin[4], R1 = fin[5], R2 = fin[6], R3 = fin[7];

    // ---- pass 3: write out[h, n] ----
    for (int i = st + threadIdx.x; i < en; i += SOFT_THREADS) {
        float4 v = reinterpret_cast<const float4*>(z)[i];
        out[0 * (size_t)N + i] = expf(v.x - M0) * R0;
        out[1 * (size_t)N + i] = expf(v.y - M1) * R1;
        out[2 * (size_t)N + i] = expf(v.z - M2) * R2;
        out[3 * (size_t)N + i] = expf(v.w - M3) * R3;
    }
}

// ---------------------------------------------------------------------------
// Inputs (metadata order): 0=inputs[N,40] f32, 1=segment_ids[N] i32,
// 2=lengths[S] i32 (unused by reference), 3..10 = W1,b1,W2,b2,W3,b3,Wr,br
// (all cancel out of the output), 11=W_k[168,256] f32, 12=W_q[4,64] f32.
// Output: [HEADS, N, 1] f32.
// ---------------------------------------------------------------------------
extern "C" void kernel_launch(void* const* d_in, const int* in_sizes, int n_in,
                              void* d_out, int out_size) {
    const float* x   = (const float*)d_in[0];
    const int*   seg = (const int*)d_in[1];
    const float* Wk  = (const float*)d_in[11];
    const float* Wq  = (const float*)d_in[12];
    float* out = (float*)d_out;

    const int N = in_sizes[1];   // 500000
    const int S = in_sizes[2];   // 2048

    float* z;
    cudaGetSymbolAddress((void**)&z, g_z);

    k_fold<<<1, DIN * HEADS>>>(Wk, Wq);
    k_z<<<(N + 255) / 256, 256>>>(x, z, N);
    k_softmax<<<S, SOFT_THREADS>>>(z, seg, out, N);
}